// round 3
// baseline (speedup 1.0000x reference)
#include <cuda_runtime.h>
#include <math.h>

#define NB 4          // batch / classes
#define DD 512        // feature dim
#define CCB 2         // compute blocks (256 columns each)
#define TPB 256
#define NCOPY 1182    // copy blocks: CCB + NCOPY = 1184 = 148 SMs * 8 blocks
#define ALPHA_IT 0.7f
#define BETA_IT  0.5f

__global__ void __launch_bounds__(TPB, 8)
graphlearner_fused(const float* __restrict__ bt,    // base_text_features (4,512)
                   const float* __restrict__ bi,    // base_img_features  (4,512)
                   const float* __restrict__ img,   // img_feature (40960,512)
                   const float* __restrict__ Wtt,   // (512,512)
                   const float* __restrict__ btt,   // (4,512)
                   const float* __restrict__ Wit,   // (512,512)
                   const float* __restrict__ bit_,  // (4,512)
                   float* __restrict__ out,         // refined(4,512) ++ img(40960,512)
                   long long n_img_f4)
{
    const int tid = threadIdx.x;

    // ---------------- copy blocks: stream img_feature -> out + 2048 --------
    if (blockIdx.x >= CCB) {
        const float4* __restrict__ src = (const float4*)img;
        float4* __restrict__ dst = (float4*)(out + NB * DD);
        const int cb = blockIdx.x - CCB;                 // 0..NCOPY-1
        const long long chunk = (n_img_f4 + NCOPY - 1) / NCOPY;
        const long long start = (long long)cb * chunk;
        const long long end   = (start + chunk < n_img_f4) ? (start + chunk)
                                                           : n_img_f4;
        long long i = start + tid;
        // 4 independent float4 loads in flight before the stores
        for (; i + 3 * TPB < end; i += 4 * TPB) {
            float4 a0 = src[i];
            float4 a1 = src[i + TPB];
            float4 a2 = src[i + 2 * TPB];
            float4 a3 = src[i + 3 * TPB];
            dst[i]           = a0;
            dst[i + TPB]     = a1;
            dst[i + 2 * TPB] = a2;
            dst[i + 3 * TPB] = a3;
        }
        for (; i < end; i += TPB)
            dst[i] = src[i];
        return;
    }

    // ---------------- compute blocks (~16.5 KB smem) -----------------------
    __shared__ float bt_s[NB][DD];
    __shared__ float bi_s[NB][DD];
    __shared__ float raw[3][NB][NB];   // 0: bt.bt  1: bt.bi  2: bi.bi
    __shared__ float c_tt[NB][5];
    __shared__ float c_it[NB][5];

    for (int i = tid; i < NB * DD; i += TPB) {
        ((float*)bt_s)[i] = bt[i];
        ((float*)bi_s)[i] = bi[i];
    }
    __syncthreads();

    // 48 dot products (3 gram matrices, 4x4 each), one warp per dot, 8 warps
    {
        const int warp = tid >> 5, lane = tid & 31;
        for (int q = warp; q < 48; q += 8) {
            const int mat = q >> 4, i = (q & 15) >> 2, j = q & 3;
            const float* a = (mat == 2) ? bi_s[i] : bt_s[i];
            const float* c = (mat == 0) ? bt_s[j] : bi_s[j];
            float s = 0.f;
            for (int k = lane; k < DD; k += 32) s += a[k] * c[k];
            #pragma unroll
            for (int off = 16; off > 0; off >>= 1)
                s += __shfl_down_sync(0xffffffffu, s, off);
            if (lane == 0) raw[mat][i][j] = s;
        }
    }
    __syncthreads();

    // 8 tiny graphs: threads 0..3 -> tt for b, threads 4..7 -> it for b
    if (tid < 8) {
        const int b = tid & 3;
        const bool is_it = tid >= 4;
        float nt[NB], ni[NB];
        #pragma unroll
        for (int i = 0; i < NB; i++) {
            nt[i] = fmaxf(sqrtf(raw[0][i][i]), 1e-12f);
            ni[i] = fmaxf(sqrtf(raw[2][i][i]), 1e-12f);
        }
        float e[5][5];
        if (!is_it) {
            e[0][0] = raw[0][b][b] / (nt[b] * nt[b]);
            #pragma unroll
            for (int m = 1; m < 5; m++) {
                e[0][m] = raw[0][b][m - 1] / (nt[b] * nt[m - 1]);
                e[m][0] = raw[0][m - 1][b] / (nt[m - 1] * nt[b]);
            }
            #pragma unroll
            for (int n = 1; n < 5; n++)
                #pragma unroll
                for (int m = 1; m < 5; m++)
                    e[n][m] = raw[0][n - 1][m - 1] / (nt[n - 1] * nt[m - 1]);
        } else {
            e[0][0] = raw[0][b][b] / (nt[b] * nt[b]);
            #pragma unroll
            for (int m = 1; m < 5; m++) {
                e[0][m] = raw[1][b][m - 1] / (nt[b] * ni[m - 1]);
                e[m][0] = e[0][m];
            }
            #pragma unroll
            for (int n = 1; n < 5; n++)
                #pragma unroll
                for (int m = 1; m < 5; m++)
                    e[n][m] = raw[2][n - 1][m - 1] / (ni[n - 1] * ni[m - 1]);
        }
        float adj[5][5], deg[5];
        #pragma unroll
        for (int n = 0; n < 5; n++) {
            deg[n] = 0.f;
            #pragma unroll
            for (int m = 0; m < 5; m++) {
                adj[n][m] = fmaxf(e[n][m], 0.f) + ((n == m) ? 1.f : 0.f);
                deg[n] += adj[n][m];
            }
        }
        float dinv[5];
        #pragma unroll
        for (int n = 0; n < 5; n++)
            dinv[n] = (deg[n] > 0.f) ? (1.f / sqrtf(deg[n])) : 0.f;
        float* cc = is_it ? c_it[b] : c_tt[b];
        #pragma unroll
        for (int m = 0; m < 5; m++)
            cc[m] = dinv[0] * adj[0][m] * dinv[m];
    }
    __syncthreads();

    // dual GEMV with summation-order swap: 12 accumulators per column thread.
    const int d = blockIdx.x * TPB + tid;   // 0..511
    float u_tt[NB]  = {0.f, 0.f, 0.f, 0.f};
    float u_itb[NB] = {0.f, 0.f, 0.f, 0.f};
    float u_iti[NB] = {0.f, 0.f, 0.f, 0.f};
    #pragma unroll 2
    for (int k = 0; k < DD; k++) {
        const float wt = Wtt[k * DD + d];
        const float wi = Wit[k * DD + d];
        #pragma unroll
        for (int m = 0; m < NB; m++) {
            u_tt[m]  = fmaf(wt, bt_s[m][k], u_tt[m]);
            u_itb[m] = fmaf(wi, bt_s[m][k], u_itb[m]);
            u_iti[m] = fmaf(wi, bi_s[m][k], u_iti[m]);
        }
    }

    #pragma unroll
    for (int b = 0; b < NB; b++) {
        float att = c_tt[b][0] * u_tt[b];
        float ait = c_it[b][0] * u_itb[b];
        #pragma unroll
        for (int j = 0; j < NB; j++) {
            att = fmaf(c_tt[b][j + 1], u_tt[j],  att);
            ait = fmaf(c_it[b][j + 1], u_iti[j], ait);
        }
        const float stt = att + btt[b * DD + d];
        const float sit = ait + bit_[b * DD + d];
        const float g = ALPHA_IT * tanhf(stt) + (1.f - ALPHA_IT) * tanhf(sit);
        out[b * DD + d] = BETA_IT * bt_s[b][d] + (1.f - BETA_IT) * g;
    }
}

extern "C" void kernel_launch(void* const* d_in, const int* in_sizes, int n_in,
                              void* d_out, int out_size) {
    const float* bt   = (const float*)d_in[0];
    const float* bi   = (const float*)d_in[1];
    const float* img  = (const float*)d_in[2];
    const float* Wtt  = (const float*)d_in[3];
    const float* btt  = (const float*)d_in[4];
    const float* Wit  = (const float*)d_in[5];
    const float* bit_ = (const float*)d_in[6];
    float* out = (float*)d_out;

    const long long n_img    = (long long)in_sizes[2];   // 40960*512
    const long long n_img_f4 = n_img / 4;

    dim3 grid(CCB + NCOPY), block(TPB);                  // 1184 = 148*8
    graphlearner_fused<<<grid, block>>>(bt, bi, img, Wtt, btt, Wit, bit_,
                                        out, n_img_f4);
}

// round 4
// speedup vs baseline: 2.9266x; 2.9266x over previous
#include <cuda_runtime.h>
#include <math.h>

#define NB 4          // batch / classes
#define DD 512        // feature dim
#define TPB 256
#define ALPHA_IT 0.7f
#define BETA_IT  0.5f

// 8 blocks x 256 threads. Each block independently computes the tiny graph
// coefficients (gram matrices + normalized adjacency row 0), then its own
// 64 output columns of the dual GEMV + tanh + blend.
__global__ void __launch_bounds__(TPB)
graphlearner_compute(const float* __restrict__ bt,    // base_text_features (4,512)
                     const float* __restrict__ bi,    // base_img_features  (4,512)
                     const float* __restrict__ Wtt,   // (512,512)
                     const float* __restrict__ btt,   // (4,512)
                     const float* __restrict__ Wit,   // (512,512)
                     const float* __restrict__ bit_,  // (4,512)
                     float* __restrict__ out)         // refined (4,512)
{
    const int tid = threadIdx.x;

    __shared__ float bt_s[NB][DD];
    __shared__ float bi_s[NB][DD];
    __shared__ float v_tt[NB][DD];
    __shared__ float v_it[NB][DD];
    __shared__ float raw[3][NB][NB];   // 0: bt.bt  1: bt.bi  2: bi.bi
    __shared__ float c_tt[NB][5];
    __shared__ float c_it[NB][5];
    __shared__ float pacc[4][64][8];

    for (int i = tid; i < NB * DD; i += TPB) {
        ((float*)bt_s)[i] = bt[i];
        ((float*)bi_s)[i] = bi[i];
    }
    __syncthreads();

    // 48 dot products (3 gram matrices, 4x4 each), one warp per dot, 8 warps
    {
        const int warp = tid >> 5, lane = tid & 31;
        for (int q = warp; q < 48; q += 8) {
            const int mat = q >> 4, i = (q & 15) >> 2, j = q & 3;
            const float* a = (mat == 2) ? bi_s[i] : bt_s[i];
            const float* c = (mat == 0) ? bt_s[j] : bi_s[j];
            float s = 0.f;
            for (int k = lane; k < DD; k += 32) s += a[k] * c[k];
            #pragma unroll
            for (int off = 16; off > 0; off >>= 1)
                s += __shfl_down_sync(0xffffffffu, s, off);
            if (lane == 0) raw[mat][i][j] = s;
        }
    }
    __syncthreads();

    // 8 tiny graphs: threads 0..3 -> tt for b, threads 4..7 -> it for b
    if (tid < 8) {
        const int b = tid & 3;
        const bool is_it = tid >= 4;
        float nt[NB], ni[NB];
        #pragma unroll
        for (int i = 0; i < NB; i++) {
            nt[i] = fmaxf(sqrtf(raw[0][i][i]), 1e-12f);
            ni[i] = fmaxf(sqrtf(raw[2][i][i]), 1e-12f);
        }
        float e[5][5];
        if (!is_it) {
            e[0][0] = raw[0][b][b] / (nt[b] * nt[b]);
            #pragma unroll
            for (int m = 1; m < 5; m++) {
                e[0][m] = raw[0][b][m - 1] / (nt[b] * nt[m - 1]);
                e[m][0] = raw[0][m - 1][b] / (nt[m - 1] * nt[b]);
            }
            #pragma unroll
            for (int n = 1; n < 5; n++)
                #pragma unroll
                for (int m = 1; m < 5; m++)
                    e[n][m] = raw[0][n - 1][m - 1] / (nt[n - 1] * nt[m - 1]);
        } else {
            e[0][0] = raw[0][b][b] / (nt[b] * nt[b]);
            #pragma unroll
            for (int m = 1; m < 5; m++) {
                e[0][m] = raw[1][b][m - 1] / (nt[b] * ni[m - 1]);
                e[m][0] = e[0][m];
            }
            #pragma unroll
            for (int n = 1; n < 5; n++)
                #pragma unroll
                for (int m = 1; m < 5; m++)
                    e[n][m] = raw[2][n - 1][m - 1] / (ni[n - 1] * ni[m - 1]);
        }
        float adj[5][5], deg[5];
        #pragma unroll
        for (int n = 0; n < 5; n++) {
            deg[n] = 0.f;
            #pragma unroll
            for (int m = 0; m < 5; m++) {
                adj[n][m] = fmaxf(e[n][m], 0.f) + ((n == m) ? 1.f : 0.f);
                deg[n] += adj[n][m];
            }
        }
        float dinv[5];
        #pragma unroll
        for (int n = 0; n < 5; n++)
            dinv[n] = (deg[n] > 0.f) ? (1.f / sqrtf(deg[n])) : 0.f;
        float* cc = is_it ? c_it[b] : c_tt[b];
        #pragma unroll
        for (int m = 0; m < 5; m++)
            cc[m] = dinv[0] * adj[0][m] * dinv[m];
    }
    __syncthreads();

    // combined vectors v[b] = c[b,0]*node0 + sum_j c[b,j+1]*node_{j+1}
    for (int i = tid; i < NB * DD; i += TPB) {
        const int b = i / DD, k = i % DD;
        float vt = c_tt[b][0] * bt_s[b][k];
        float vi = c_it[b][0] * bt_s[b][k];
        #pragma unroll
        for (int j = 0; j < 4; j++) {
            vt += c_tt[b][j + 1] * bt_s[j][k];
            vi += c_it[b][j + 1] * bi_s[j][k];
        }
        v_tt[b][k] = vt;
        v_it[b][k] = vi;
    }
    __syncthreads();

    // dual GEMV: 4 k-splits x 64 columns per block
    const int col = tid & 63;
    const int ksp = tid >> 6;
    const int d   = blockIdx.x * 64 + col;
    float att[NB] = {0.f, 0.f, 0.f, 0.f};
    float ait[NB] = {0.f, 0.f, 0.f, 0.f};
    const int k0 = ksp * 128;
    #pragma unroll 8
    for (int kk = 0; kk < 128; kk++) {
        const int k = k0 + kk;
        const float wt = Wtt[k * DD + d];
        const float wi = Wit[k * DD + d];
        #pragma unroll
        for (int b = 0; b < NB; b++) {
            att[b] += v_tt[b][k] * wt;
            ait[b] += v_it[b][k] * wi;
        }
    }
    #pragma unroll
    for (int b = 0; b < NB; b++) {
        pacc[ksp][col][b]     = att[b];
        pacc[ksp][col][4 + b] = ait[b];
    }
    __syncthreads();

    if (ksp == 0) {
        #pragma unroll
        for (int b = 0; b < NB; b++) {
            float stt = pacc[0][col][b] + pacc[1][col][b] +
                        pacc[2][col][b] + pacc[3][col][b] + btt[b * DD + d];
            float sit = pacc[0][col][4 + b] + pacc[1][col][4 + b] +
                        pacc[2][col][4 + b] + pacc[3][col][4 + b] + bit_[b * DD + d];
            float g = ALPHA_IT * tanhf(stt) + (1.f - ALPHA_IT) * tanhf(sit);
            out[b * DD + d] = BETA_IT * bt_s[b][d] + (1.f - BETA_IT) * g;
        }
    }
}

extern "C" void kernel_launch(void* const* d_in, const int* in_sizes, int n_in,
                              void* d_out, int out_size) {
    const float* bt   = (const float*)d_in[0];
    const float* bi   = (const float*)d_in[1];
    const float* img  = (const float*)d_in[2];
    const float* Wtt  = (const float*)d_in[3];
    const float* btt  = (const float*)d_in[4];
    const float* Wit  = (const float*)d_in[5];
    const float* bit_ = (const float*)d_in[6];
    float* out = (float*)d_out;

    // 1) tiny graph + dual GEMV -> refined (first 2048 floats of out)
    graphlearner_compute<<<8, TPB>>>(bt, bi, Wtt, btt, Wit, bit_, out);

    // 2) bulk passthrough: img_feature (84 MB) -> out + 2048, via the
    //    driver-optimized D2D copy (graph-capturable, no allocation)
    const size_t n_img_bytes = (size_t)in_sizes[2] * sizeof(float);
    cudaMemcpyAsync(out + NB * DD, img, n_img_bytes, cudaMemcpyDeviceToDevice);
}

// round 5
// speedup vs baseline: 3.9685x; 1.3560x over previous
#include <cuda_runtime.h>
#include <math.h>

#define NB   4        // batch / classes
#define DD   512      // feature dim
#define TPB  128      // threads per block
#define GRID 16       // compute blocks
#define CPB  32       // output columns per block (GRID*CPB = 512)
#define F4G  8        // float4 column-groups per block (CPB/4)
#define KSP  16       // k-split factor (TPB / F4G)
#define KPER 32       // k iterations per thread (DD / KSP)
#define ALPHA_IT 0.7f
#define BETA_IT  0.5f

// 16 blocks x 128 threads. Each block redundantly computes the tiny graph
// coefficients, then its own 32 output columns of the dual GEMV (float4
// weight loads, 16-way k-split) + tanh + blend.
__global__ void __launch_bounds__(TPB)
graphlearner_compute(const float* __restrict__ bt,    // (4,512)
                     const float* __restrict__ bi,    // (4,512)
                     const float* __restrict__ Wtt,   // (512,512)
                     const float* __restrict__ btt,   // (4,512)
                     const float* __restrict__ Wit,   // (512,512)
                     const float* __restrict__ bit_,  // (4,512)
                     float* __restrict__ out)         // refined (4,512)
{
    const int tid = threadIdx.x;

    __shared__ float bt_s[NB][DD];                    // 8 KB, live to end
    __shared__ float v_tt[NB][DD];                    // 8 KB
    __shared__ float v_it[NB][DD];                    // 8 KB
    // 16 KB buffer: first bi_s (4x512 floats), later the two pacc arrays
    __shared__ __align__(16) float buf[4096];
    __shared__ float raw[3][NB][NB];
    __shared__ float c_tt[NB][5];
    __shared__ float c_it[NB][5];

    float* bi_s = buf;                                // [NB][DD] view

    // ---- load bt, bi (float4, coalesced) ----
    {
        const float4* bt4 = (const float4*)bt;
        const float4* bi4 = (const float4*)bi;
        float4* bts4 = (float4*)bt_s;
        float4* bis4 = (float4*)bi_s;
        #pragma unroll
        for (int i = tid; i < NB * DD / 4; i += TPB) {
            bts4[i] = bt4[i];
            bis4[i] = bi4[i];
        }
    }
    __syncthreads();

    // ---- 48 dot products (3 gram matrices), float4 LDS, 4 warps ----
    {
        const int warp = tid >> 5, lane = tid & 31;
        for (int q = warp; q < 48; q += 4) {
            const int mat = q >> 4, i = (q & 15) >> 2, j = q & 3;
            const float4* a4 = (const float4*)((mat == 2) ? (bi_s + i * DD)
                                                          : bt_s[i]);
            const float4* c4 = (const float4*)((mat == 0) ? bt_s[j]
                                                          : (bi_s + j * DD));
            float s = 0.f;
            #pragma unroll
            for (int jj = 0; jj < 4; jj++) {
                float4 av = a4[lane + 32 * jj];
                float4 cv = c4[lane + 32 * jj];
                s = fmaf(av.x, cv.x, s);
                s = fmaf(av.y, cv.y, s);
                s = fmaf(av.z, cv.z, s);
                s = fmaf(av.w, cv.w, s);
            }
            #pragma unroll
            for (int off = 16; off > 0; off >>= 1)
                s += __shfl_down_sync(0xffffffffu, s, off);
            if (lane == 0) raw[mat][i][j] = s;
        }
    }
    __syncthreads();

    // ---- 8 tiny graphs: row-0 normalized-adjacency coefficients ----
    if (tid < 8) {
        const int b = tid & 3;
        const bool is_it = tid >= 4;
        float nt[NB], ni[NB];
        #pragma unroll
        for (int i = 0; i < NB; i++) {
            nt[i] = fmaxf(sqrtf(raw[0][i][i]), 1e-12f);
            ni[i] = fmaxf(sqrtf(raw[2][i][i]), 1e-12f);
        }
        float e[5][5];
        if (!is_it) {
            e[0][0] = raw[0][b][b] / (nt[b] * nt[b]);
            #pragma unroll
            for (int m = 1; m < 5; m++) {
                e[0][m] = raw[0][b][m - 1] / (nt[b] * nt[m - 1]);
                e[m][0] = raw[0][m - 1][b] / (nt[m - 1] * nt[b]);
            }
            #pragma unroll
            for (int n = 1; n < 5; n++)
                #pragma unroll
                for (int m = 1; m < 5; m++)
                    e[n][m] = raw[0][n - 1][m - 1] / (nt[n - 1] * nt[m - 1]);
        } else {
            e[0][0] = raw[0][b][b] / (nt[b] * nt[b]);
            #pragma unroll
            for (int m = 1; m < 5; m++) {
                e[0][m] = raw[1][b][m - 1] / (nt[b] * ni[m - 1]);
                e[m][0] = e[0][m];
            }
            #pragma unroll
            for (int n = 1; n < 5; n++)
                #pragma unroll
                for (int m = 1; m < 5; m++)
                    e[n][m] = raw[2][n - 1][m - 1] / (ni[n - 1] * ni[m - 1]);
        }
        float adj[5][5], deg[5];
        #pragma unroll
        for (int n = 0; n < 5; n++) {
            deg[n] = 0.f;
            #pragma unroll
            for (int m = 0; m < 5; m++) {
                adj[n][m] = fmaxf(e[n][m], 0.f) + ((n == m) ? 1.f : 0.f);
                deg[n] += adj[n][m];
            }
        }
        float dinv[5];
        #pragma unroll
        for (int n = 0; n < 5; n++)
            dinv[n] = (deg[n] > 0.f) ? (1.f / sqrtf(deg[n])) : 0.f;
        float* cc = is_it ? c_it[b] : c_tt[b];
        #pragma unroll
        for (int m = 0; m < 5; m++)
            cc[m] = dinv[0] * adj[0][m] * dinv[m];
    }
    __syncthreads();

    // ---- combined vectors v[b] = c[b,0]*node0 + sum_j c[b,j+1]*node_j ----
    #pragma unroll
    for (int i = tid; i < NB * DD; i += TPB) {
        const int b = i >> 9, k = i & (DD - 1);
        float vt = c_tt[b][0] * bt_s[b][k];
        float vi = c_it[b][0] * bt_s[b][k];
        #pragma unroll
        for (int j = 0; j < 4; j++) {
            vt = fmaf(c_tt[b][j + 1], bt_s[j][k],       vt);
            vi = fmaf(c_it[b][j + 1], bi_s[j * DD + k], vi);
        }
        v_tt[b][k] = vt;
        v_it[b][k] = vi;
    }
    __syncthreads();   // also retires all bi_s reads before buf is reused

    // ---- dual GEMV: float4 weight loads, 16-way k-split ----
    // pacc layout in buf: tt partials then it partials,
    // each [KSP][F4G][NB] of float4  (16*8*4*16B = 8 KB each)
    float4* pacc_tt = (float4*)buf;
    float4* pacc_it = pacc_tt + KSP * F4G * NB;

    const int f4g = tid & (F4G - 1);
    const int ksp = tid >> 3;                  // 0..15
    const int d0  = blockIdx.x * CPB + f4g * 4;

    float4 att[NB], ait[NB];
    #pragma unroll
    for (int b = 0; b < NB; b++) {
        att[b] = make_float4(0.f, 0.f, 0.f, 0.f);
        ait[b] = make_float4(0.f, 0.f, 0.f, 0.f);
    }
    const int kbase = ksp * KPER;
    #pragma unroll 8
    for (int kk = 0; kk < KPER; kk++) {
        const int k = kbase + kk;
        const float4 wt = *(const float4*)(Wtt + (size_t)k * DD + d0);
        const float4 wi = *(const float4*)(Wit + (size_t)k * DD + d0);
        #pragma unroll
        for (int b = 0; b < NB; b++) {
            const float vt = v_tt[b][k];
            const float vi = v_it[b][k];
            att[b].x = fmaf(vt, wt.x, att[b].x);
            att[b].y = fmaf(vt, wt.y, att[b].y);
            att[b].z = fmaf(vt, wt.z, att[b].z);
            att[b].w = fmaf(vt, wt.w, att[b].w);
            ait[b].x = fmaf(vi, wi.x, ait[b].x);
            ait[b].y = fmaf(vi, wi.y, ait[b].y);
            ait[b].z = fmaf(vi, wi.z, ait[b].z);
            ait[b].w = fmaf(vi, wi.w, ait[b].w);
        }
    }
    #pragma unroll
    for (int b = 0; b < NB; b++) {
        pacc_tt[(ksp * F4G + f4g) * NB + b] = att[b];
        pacc_it[(ksp * F4G + f4g) * NB + b] = ait[b];
    }
    __syncthreads();

    // ---- reduction + tanh + blend: one thread per (d_local, b) ----
    {
        const int d_local = tid & (CPB - 1);   // 0..31
        const int b       = tid >> 5;          // 0..3
        const int fg      = d_local >> 2;
        const int comp    = d_local & 3;
        const int d       = blockIdx.x * CPB + d_local;

        const float* pt = (const float*)pacc_tt;
        const float* pi = (const float*)pacc_it;
        float stt = btt[b * DD + d];
        float sit = bit_[b * DD + d];
        #pragma unroll
        for (int s = 0; s < KSP; s++) {
            const int idx = ((s * F4G + fg) * NB + b) * 4 + comp;
            stt += pt[idx];
            sit += pi[idx];
        }
        const float g = ALPHA_IT * tanhf(stt) + (1.f - ALPHA_IT) * tanhf(sit);
        out[b * DD + d] = BETA_IT * bt_s[b][d] + (1.f - BETA_IT) * g;
    }
}

extern "C" void kernel_launch(void* const* d_in, const int* in_sizes, int n_in,
                              void* d_out, int out_size) {
    const float* bt   = (const float*)d_in[0];
    const float* bi   = (const float*)d_in[1];
    const float* img  = (const float*)d_in[2];
    const float* Wtt  = (const float*)d_in[3];
    const float* btt  = (const float*)d_in[4];
    const float* Wit  = (const float*)d_in[5];
    const float* bit_ = (const float*)d_in[6];
    float* out = (float*)d_out;

    // 1) tiny graph + dual GEMV -> refined (first 2048 floats of out)
    graphlearner_compute<<<GRID, TPB>>>(bt, bi, Wtt, btt, Wit, bit_, out);

    // 2) bulk passthrough: img_feature (84 MB) -> out + 2048 via the
    //    driver-optimized D2D copy (graph-capturable, allocation-free)
    const size_t n_img_bytes = (size_t)in_sizes[2] * sizeof(float);
    cudaMemcpyAsync(out + NB * DD, img, n_img_bytes, cudaMemcpyDeviceToDevice);
}